// round 14
// baseline (speedup 1.0000x reference)
#include <cuda_runtime.h>
#include <cuda_fp16.h>
#include <cstdint>
#include <cmath>

// ============================================================================
// CGRU cell, B=1024, UNITS=2048 — Gauss 3-mult complex GEMM, FP16 mma.sync.
// v9: gemm_big retiled to 128x256 CTA (256 thr, warps 2m x 4n of 64x64) to
// relieve the smem-crossbar bind (48KB->44KB per M MACs). Schedule = round 13.
// ============================================================================

#define TU4 512                          // uint4 per 128x32 fp16 tile
#define ASTRIDE ((size_t)128 * TU4)      // u4 per (unit,batch): 128 kb slots
#define HSTRIDE ((size_t)64 * TU4)       // u4 per (unit,batch): 64 kb slots
#define BSTR HSTRIDE

// ------------------------------ scratch (device globals, allocation-free) --
__device__ uint4 g_AH [(size_t)8  * 3 * ASTRIDE];  // [A|H] fragments  (25MB)
__device__ uint4 g_WZR[(size_t)32 * 3 * ASTRIDE];  // [[Kzr],[Rzr]]    (100MB)
__device__ uint4 g_WH [(size_t)16 * 3 * HSTRIDE];  // Kh               (25MB)
__device__ uint4 g_WRH[(size_t)16 * 3 * HSTRIDE];  // Rh               (25MB)
__device__ uint4 g_RHF[(size_t)8  * 3 * HSTRIDE];  // (r*h) fragments  (12.6MB)
__device__ float g_ZR [(size_t)3 * 1024 * 4096];   // zr GEMM out (50MB)
__device__ float g_XH [(size_t)3 * 1024 * 2048];   // x_h GEMM out (25MB)
__device__ float g_R  [(size_t)6 * 1024 * 2048];   // HH GEMM out (split-K x2)
__device__ float g_Z  [(size_t)1024 * 4096];

// ----------------------------------------------------------------- helpers --
__device__ __forceinline__ void cp16s(uint32_t d, const void* s) {
    asm volatile("cp.async.cg.shared.global [%0], [%1], 16;" :: "r"(d), "l"(s));
}
__device__ __forceinline__ uint32_t smem_u32(const void* p) {
    uint32_t a;
    asm("{ .reg .u64 t; cvta.to.shared.u64 t, %1; cvt.u32.u64 %0, t; }" : "=r"(a) : "l"(p));
    return a;
}
__device__ __forceinline__ void mma_f16(float* c, const uint32_t* a, uint32_t b0, uint32_t b1) {
    asm volatile(
        "mma.sync.aligned.m16n8k16.row.col.f32.f16.f16.f32 "
        "{%0,%1,%2,%3},{%4,%5,%6,%7},{%8,%9},{%0,%1,%2,%3};"
        : "+f"(c[0]), "+f"(c[1]), "+f"(c[2]), "+f"(c[3])
        : "r"(a[0]), "r"(a[1]), "r"(a[2]), "r"(a[3]), "r"(b0), "r"(b1));
}
__device__ __forceinline__ uint32_t packh2(float a, float b) {
    __half2 h = __floats2half2_rn(a, b);
    return *(uint32_t*)&h;
}

// ============================================================================
// prep_w_sub: weight fragments.
//   mode 0 (5120 blocks): b<4096 -> WZR (panels 0-31, both matrices);
//                         b>=4096 -> WH (mat0, panels 32-47)
//   mode 1 (1024 blocks): WRH (mat1, panels 32-47)
// ============================================================================
#define PWS 136

__global__ __launch_bounds__(256) void prep_w_sub(
    const float* __restrict__ rk,  const float* __restrict__ ik,
    const float* __restrict__ rrk, const float* __restrict__ irk,
    int mode)
{
    __shared__ float sr[32 * PWS], si[32 * PWS];
    const int tid = threadIdx.x;
    const int b = blockIdx.x;

    int mat, panel, kb;
    if (mode == 0) {
        if (b < 4096) {
            mat = b >> 11;
            const int rem = b & 2047;
            panel = rem >> 6;
            kb = rem & 63;
        } else {
            mat = 0;
            panel = 32 + ((b - 4096) >> 6);
            kb = b & 63;
        }
    } else {
        mat = 1;
        panel = 32 + (b >> 6);
        kb = b & 63;
    }

    const float* Wr = mat ? rrk : rk;
    const float* Wi = mat ? irk : ik;
    const size_t gbase = (size_t)(kb * 32) * 6144 + panel * 128;

#pragma unroll
    for (int t = 0; t < 4; t++) {
        const int idx = tid + t * 256;
        const int row = idx >> 5, c4 = idx & 31;
        const size_t ga = gbase + (size_t)row * 6144 + c4 * 4;
        *(float4*)&sr[row * PWS + c4 * 4] = *(const float4*)&Wr[ga];
        *(float4*)&si[row * PWS + c4 * 4] = *(const float4*)&Wi[ga];
    }
    __syncthreads();

    uint4* O;
    size_t obase, bstr;
    if (panel < 32) {
        O = g_WZR;
        obase = ((size_t)(panel * 3) * 128 + mat * 64 + kb) * TU4;
        bstr = ASTRIDE;
    } else {
        O = mat ? g_WRH : g_WH;
        obase = ((size_t)((panel - 32) * 3) * 64 + kb) * TU4;
        bstr = HSTRIDE;
    }

#pragma unroll
    for (int t = 0; t < 2; t++) {
        const int x = tid + t * 256;
        const int n16 = x >> 6, k16 = (x >> 5) & 1, lane = x & 31;
        const int grp = lane >> 2, tig = lane & 3;
        const int c = n16 * 16 + grp;
        const int k0 = k16 * 16 + tig * 2;

        float wr[8], wi[8];
#pragma unroll
        for (int hc = 0; hc < 2; hc++) {
            const int cc = c + hc * 8;
            wr[hc*4+0] = sr[k0 * PWS + cc];       wi[hc*4+0] = si[k0 * PWS + cc];
            wr[hc*4+1] = sr[(k0+1) * PWS + cc];   wi[hc*4+1] = si[(k0+1) * PWS + cc];
            wr[hc*4+2] = sr[(k0+8) * PWS + cc];   wi[hc*4+2] = si[(k0+8) * PWS + cc];
            wr[hc*4+3] = sr[(k0+9) * PWS + cc];   wi[hc*4+3] = si[(k0+9) * PWS + cc];
        }
        uint4 v0, v1, v2;
        v0.x = packh2(wr[0], wr[1]); v0.y = packh2(wr[2], wr[3]);
        v0.z = packh2(wr[4], wr[5]); v0.w = packh2(wr[6], wr[7]);
        v1.x = packh2(wi[0], wi[1]); v1.y = packh2(wi[2], wi[3]);
        v1.z = packh2(wi[4], wi[5]); v1.w = packh2(wi[6], wi[7]);
        v2.x = packh2(wr[0]+wi[0], wr[1]+wi[1]); v2.y = packh2(wr[2]+wi[2], wr[3]+wi[3]);
        v2.z = packh2(wr[4]+wi[4], wr[5]+wi[5]); v2.w = packh2(wr[6]+wi[6], wr[7]+wi[7]);

        O[obase + x]            = v0;
        O[obase + bstr + x]     = v1;
        O[obase + 2 * bstr + x] = v2;
    }
}

// ============================================================================
// prep_a: A-fragments into concat layout [mp(8)][batch(3)][kb(128)][512 u4]:
//   src 0 (inputs) -> kb 0-63, src 1 (h) -> kb 64-127.
// ============================================================================
#define PAS 36

__global__ __launch_bounds__(256) void prep_a(
    const float* __restrict__ in0, const float* __restrict__ in1)
{
    __shared__ float s0[128 * PAS], s1[128 * PAS];
    const int tid = threadIdx.x;
    const int b = blockIdx.x;
    const int src = b >> 9;
    const int rem = b & 511;
    const int mp = rem >> 6;
    const int kb = rem & 63;

    const float* A = src ? in1 : in0;

#pragma unroll
    for (int t = 0; t < 8; t++) {
        const int idx = tid + t * 256;
        const int half_ = idx >> 10;
        const int i2 = idx & 1023;
        const int row = i2 >> 3, c4 = i2 & 7;
        const float4 v = *(const float4*)&A[(size_t)(mp * 128 + row) * 4096
                                            + half_ * 2048 + kb * 32 + c4 * 4];
        float* s = half_ ? s1 : s0;
        *(float4*)&s[row * PAS + c4 * 4] = v;
    }
    __syncthreads();

    const size_t obase = ((size_t)(mp * 3) * 128 + src * 64 + kb) * TU4;

#pragma unroll
    for (int t = 0; t < 2; t++) {
        const int x = tid + t * 256;
        const int m16 = x >> 6, k16 = (x >> 5) & 1, lane = x & 31;
        const int grp = lane >> 2, tig = lane & 3;
        const int r = m16 * 16 + grp;
        const int k0 = k16 * 16 + tig * 2;

        float re[8], im[8];
#pragma unroll
        for (int hk = 0; hk < 2; hk++) {
            const int kk = k0 + hk * 8;
            re[hk*4+0] = s0[r * PAS + kk];         im[hk*4+0] = s1[r * PAS + kk];
            re[hk*4+1] = s0[r * PAS + kk + 1];     im[hk*4+1] = s1[r * PAS + kk + 1];
            re[hk*4+2] = s0[(r+8) * PAS + kk];     im[hk*4+2] = s1[(r+8) * PAS + kk];
            re[hk*4+3] = s0[(r+8) * PAS + kk + 1]; im[hk*4+3] = s1[(r+8) * PAS + kk + 1];
        }
        uint4 v0, v1, v2;
        v0.x = packh2(re[0], re[1]); v0.y = packh2(re[2], re[3]);
        v0.z = packh2(re[4], re[5]); v0.w = packh2(re[6], re[7]);
        v1.x = packh2(im[0], im[1]); v1.y = packh2(im[2], im[3]);
        v1.z = packh2(im[4], im[5]); v1.w = packh2(im[6], im[7]);
        v2.x = packh2(im[0]-re[0], im[1]-re[1]); v2.y = packh2(im[2]-re[2], im[3]-re[3]);
        v2.z = packh2(im[4]-re[4], im[5]-re[5]); v2.w = packh2(im[6]-re[6], im[7]-re[7]);

        g_AH[obase + x]               = v0;
        g_AH[obase + ASTRIDE + x]     = v1;
        g_AH[obase + 2 * ASTRIDE + x] = v2;
    }
}

// ============================================================================
// gemm_big v2: 128x256 CTA tile, 256 threads, warps 2m x 4n of 64x64.
// Stage = A 8KB + B 16KB (two panel units) = 24KB, 4 stages = 96KB.
// grid (3, 8, 24): x=batch, y=mp, z: 0-15 zr (K=128 it), 16-23 xh (K=64 it,
// scheduled last -> short final wave).
// ============================================================================
#define STAGES 4
#define STG2_BYTES 24576
#define GSMEM2 (STAGES * STG2_BYTES)     // 96KB

#define ISSUE2(kb) do {                                                        \
    const uint32_t _st = sbase + ((kb) % STAGES) * STG2_BYTES;                 \
    const uint4* _sa = At  + (size_t)(kb) * TU4;                               \
    const uint4* _b0 = Bt0 + (size_t)(kb) * TU4;                               \
    const uint4* _b1 = Bt1 + (size_t)(kb) * TU4;                               \
    cp16s(_st + tid * 16,               _sa + tid);                            \
    cp16s(_st + (tid + 256) * 16,       _sa + tid + 256);                      \
    cp16s(_st + 8192 + tid * 16,        _b0 + tid);                            \
    cp16s(_st + 8192 + (tid + 256) * 16, _b0 + tid + 256);                     \
    cp16s(_st + 16384 + tid * 16,       _b1 + tid);                            \
    cp16s(_st + 16384 + (tid + 256) * 16, _b1 + tid + 256);                    \
} while (0)

__global__ __launch_bounds__(256, 1) void gemm_big()
{
    extern __shared__ uint4 smu[];
    const uint32_t sbase = smem_u32(smu);
    const int tid = threadIdx.x, wid = tid >> 5, lane = tid & 31;
    const int grp = lane >> 2, tig = lane & 3;
    const int batch = blockIdx.x;
    const int mp = blockIdx.y;
    const int pz = blockIdx.z;

    const uint4* At = g_AH + (size_t)(mp * 3 + batch) * ASTRIDE;
    const uint4 *Bt0, *Bt1;
    float* Cb;
    int Nld, n0, kIters;
    if (pz < 16) {
        Bt0 = g_WZR + (size_t)((pz * 2) * 3 + batch) * ASTRIDE;
        Bt1 = Bt0 + 3 * ASTRIDE;
        Cb = g_ZR + (size_t)batch * 1024 * 4096;
        Nld = 4096; n0 = pz * 256; kIters = 128;
    } else {
        const int px = pz - 16;
        Bt0 = g_WH + (size_t)((px * 2) * 3 + batch) * HSTRIDE;
        Bt1 = Bt0 + 3 * HSTRIDE;
        Cb = g_XH + (size_t)batch * 1024 * 2048;
        Nld = 2048; n0 = px * 256; kIters = 64;
    }

    const int widn = wid >> 1;           // 0..3 (64-col slice)
    const int wm4 = (wid & 1) * 4;       // m16-block base within A unit
    const int wn4 = (widn & 1) * 4;      // n16-block base within B unit
    const int bunit = widn >> 1;         // B panel unit 0/1

    float acc[4][8][4];
#pragma unroll
    for (int a = 0; a < 4; a++)
#pragma unroll
        for (int b2 = 0; b2 < 8; b2++)
#pragma unroll
            for (int c = 0; c < 4; c++) acc[a][b2][c] = 0.0f;

    ISSUE2(0);
    asm volatile("cp.async.commit_group;" ::: "memory");
    ISSUE2(1);
    asm volatile("cp.async.commit_group;" ::: "memory");
    ISSUE2(2);
    asm volatile("cp.async.commit_group;" ::: "memory");

    uint4 af[2][4], bf[2][4];

    for (int kb = 0; kb < kIters; ++kb) {
        asm volatile("cp.async.wait_group 2;" ::: "memory");
        __syncthreads();

        const uint4* As = smu + (kb % STAGES) * 1536;
        const uint4* Bs = As + 512 + bunit * 512;

#pragma unroll
        for (int t = 0; t < 4; ++t) {
            af[0][t] = As[((wm4 + t) * 2) * 32 + lane];
            bf[0][t] = Bs[((wn4 + t) * 2) * 32 + lane];
        }

#pragma unroll
        for (int ks = 0; ks < 2; ++ks) {
            const int cur = ks;
            if (ks == 0) {
#pragma unroll
                for (int t = 0; t < 4; ++t) {
                    af[1][t] = As[((wm4 + t) * 2 + 1) * 32 + lane];
                    bf[1][t] = Bs[((wn4 + t) * 2 + 1) * 32 + lane];
                }
            }
#pragma unroll
            for (int tm = 0; tm < 4; ++tm) {
                const uint32_t* a = (const uint32_t*)&af[cur][tm];
#pragma unroll
                for (int p = 0; p < 4; ++p) {
                    const uint32_t* bu = (const uint32_t*)&bf[cur][p];
                    mma_f16(acc[tm][p * 2],     a, bu[0], bu[1]);
                    mma_f16(acc[tm][p * 2 + 1], a, bu[2], bu[3]);
                }
            }
        }

        if (kb + 3 < kIters) ISSUE2(kb + 3);
        asm volatile("cp.async.commit_group;" ::: "memory");
    }

#pragma unroll
    for (int tm = 0; tm < 4; ++tm) {
#pragma unroll
        for (int tn = 0; tn < 8; ++tn) {
            const int m0 = mp * 128 + (wid & 1) * 64 + tm * 16 + grp;
            const int nn = n0 + widn * 64 + tn * 8 + tig * 2;
            *(float2*)&Cb[(size_t)m0 * Nld + nn]       = make_float2(acc[tm][tn][0], acc[tm][tn][1]);
            *(float2*)&Cb[(size_t)(m0 + 8) * Nld + nn] = make_float2(acc[tm][tn][2], acc[tm][tn][3]);
        }
    }
}

// ============================================================================
// gemm_frag: HH GEMM (A=RHF, B=WRH), 128x128 tile, split-K x2 via blockIdx.z.
// ============================================================================
#define STG_BYTES 16384
#define GSMEM (STAGES * STG_BYTES)

#define ISSUE(kb) do {                                                         \
    const uint32_t _st = sbase + ((kb) % STAGES) * STG_BYTES;                  \
    const uint4* _sa = At + (size_t)(kb) * TU4;                                \
    const uint4* _sb = Bt + (size_t)(kb) * TU4;                                \
    _Pragma("unroll")                                                          \
    for (int _i = 0; _i < 4; _i++) {                                           \
        const int _o = tid + _i * 128;                                         \
        cp16s(_st + _o * 16, _sa + _o);                                        \
        cp16s(_st + 8192 + _o * 16, _sb + _o);                                 \
    }                                                                          \
} while (0)

__global__ __launch_bounds__(128, 2) void gemm_frag(
    const uint4* __restrict__ Ap, const uint4* __restrict__ Bp,
    float* __restrict__ C, int Nld, int kIters)
{
    extern __shared__ uint4 smu[];
    const uint32_t sbase = smem_u32(smu);
    const int tid = threadIdx.x, wid = tid >> 5, lane = tid & 31;
    const int grp = lane >> 2, tig = lane & 3;
    const int mp = blockIdx.y;
    const int z = blockIdx.z;
    const int batch = z % 3, half_ = z / 3;
    const int panel = blockIdx.x;
    const int kO = half_ * kIters;

    const uint4* At = Ap + (size_t)(mp * 3 + batch) * BSTR + (size_t)kO * TU4;
    const uint4* Bt = Bp + (size_t)(panel * 3 + batch) * BSTR + (size_t)kO * TU4;
    float* Cb = C + (size_t)z * 1024 * Nld;
    const int n0 = panel * 128;

    const int wm4 = (wid & 1) * 4;
    const int wn4 = (wid >> 1) * 4;

    float acc[4][8][4];
#pragma unroll
    for (int a = 0; a < 4; a++)
#pragma unroll
        for (int b2 = 0; b2 < 8; b2++)
#pragma unroll
            for (int c = 0; c < 4; c++) acc[a][b2][c] = 0.0f;

    ISSUE(0);
    asm volatile("cp.async.commit_group;" ::: "memory");
    ISSUE(1);
    asm volatile("cp.async.commit_group;" ::: "memory");
    ISSUE(2);
    asm volatile("cp.async.commit_group;" ::: "memory");

    uint4 af[2][4], bf[2][4];

    for (int kb = 0; kb < kIters; ++kb) {
        asm volatile("cp.async.wait_group 2;" ::: "memory");
        __syncthreads();

        const uint4* As = smu + (kb % STAGES) * 1024;
        const uint4* Bs = As + 512;

#pragma unroll
        for (int t = 0; t < 4; ++t) {
            af[0][t] = As[((wm4 + t) * 2) * 32 + lane];
            bf[0][t] = Bs[((wn4 + t) * 2) * 32 + lane];
        }

#pragma unroll
        for (int ks = 0; ks < 2; ++ks) {
            const int cur = ks;
            if (ks == 0) {
#pragma unroll
                for (int t = 0; t < 4; ++t) {
                    af[1][t] = As[((wm4 + t) * 2 + 1) * 32 + lane];
                    bf[1][t] = Bs[((wn4 + t) * 2 + 1) * 32 + lane];
                }
            }
#pragma unroll
            for (int tm = 0; tm < 4; ++tm) {
                const uint32_t* a = (const uint32_t*)&af[cur][tm];
#pragma unroll
                for (int p = 0; p < 4; ++p) {
                    const uint32_t* bu = (const uint32_t*)&bf[cur][p];
                    mma_f16(acc[tm][p * 2],     a, bu[0], bu[1]);
                    mma_f16(acc[tm][p * 2 + 1], a, bu[2], bu[3]);
                }
            }
        }

        if (kb + 3 < kIters) ISSUE(kb + 3);
        asm volatile("cp.async.commit_group;" ::: "memory");
    }

#pragma unroll
    for (int tm = 0; tm < 4; ++tm) {
#pragma unroll
        for (int tn = 0; tn < 8; ++tn) {
            const int m0 = mp * 128 + (wid & 1) * 64 + tm * 16 + grp;
            const int nn = n0 + (wid >> 1) * 64 + tn * 8 + tig * 2;
            *(float2*)&Cb[(size_t)m0 * Nld + nn]       = make_float2(acc[tm][tn][0], acc[tm][tn][1]);
            *(float2*)&Cb[(size_t)(m0 + 8) * Nld + nn] = make_float2(acc[tm][tn][2], acc[tm][tn][3]);
        }
    }
}

// ---------------------------------------------------------------- elementwise
__device__ __forceinline__ float hsig(float x) {
    return fminf(fmaxf(0.2f * x + 0.5f, 0.0f), 1.0f);
}

__global__ void ew_zr(const float* __restrict__ ZR, const float* __restrict__ h,
                      const float* __restrict__ rb, const float* __restrict__ ib,
                      float* __restrict__ Z, __half* __restrict__ RHp)
{
    const int i = blockIdx.x * blockDim.x + threadIdx.x;
    const int m = i >> 9;
    const int jj = (i & 511) << 2;

    const size_t PX = (size_t)1024 * 4096;
    const float* Z1 = ZR + (size_t)m * 4096;

    float4 p1z = *(const float4*)&Z1[jj],        p2z = *(const float4*)&Z1[PX + jj],
           p3z = *(const float4*)&Z1[2*PX + jj];
    float4 p1r = *(const float4*)&Z1[2048 + jj], p2r = *(const float4*)&Z1[PX + 2048 + jj],
           p3r = *(const float4*)&Z1[2*PX + 2048 + jj];

    float4 hre = *(const float4*)&h[(size_t)m * 4096 + jj];
    float4 him = *(const float4*)&h[(size_t)m * 4096 + 2048 + jj];
    float4 bzr = *(const float4*)&rb[jj],        bzi = *(const float4*)&ib[jj];
    float4 brr = *(const float4*)&rb[2048 + jj], bri = *(const float4*)&ib[2048 + jj];

    float zre[4], zim[4], vre[4], vim[4];
#pragma unroll
    for (int c = 0; c < 4; c++) {
        float P1z = (&p1z.x)[c], P2z = (&p2z.x)[c], P3z = (&p3z.x)[c];
        float P1r = (&p1r.x)[c], P2r = (&p2r.x)[c], P3r = (&p3r.x)[c];
        zre[c] = hsig(P1z + P2z + (&bzr.x)[c]);
        zim[c] = hsig(P3z + P1z - P2z + (&bzi.x)[c]);
        float rre = hsig(P1r + P2r + (&brr.x)[c]);
        float rim = hsig(P3r + P1r - P2r + (&bri.x)[c]);
        vre[c] = rre * (&hre.x)[c];
        vim[c] = rim * (&him.x)[c];
    }

    *(float4*)&Z[(size_t)m * 4096 + jj]        = make_float4(zre[0], zre[1], zre[2], zre[3]);
    *(float4*)&Z[(size_t)m * 4096 + 2048 + jj] = make_float4(zim[0], zim[1], zim[2], zim[3]);

    const int mp = m >> 7, m16 = (m >> 4) & 7;
    const int rr = m & 15, grpm = rr & 7, hi = rr >> 3;
    const int kb = jj >> 5, k16 = (jj >> 4) & 1;
    const int jmk = jj & 15, tig0 = (jmk & 7) >> 1, hiK = jmk >> 3;
    const int pos = hiK * 4 + hi * 2;
    const size_t HBSTR = (size_t)64 * 4096;
    size_t base = ((size_t)(mp * 3) * 64 + kb) * 4096
                + ((size_t)((m16 * 2 + k16) * 32 + grpm * 4) * 8) + pos;

    __half2 a0 = __floats2half2_rn(vre[0], vre[1]);
    __half2 a1 = __floats2half2_rn(vre[2], vre[3]);
    __half2 b0 = __floats2half2_rn(vim[0], vim[1]);
    __half2 b1 = __floats2half2_rn(vim[2], vim[3]);
    __half2 c0 = __floats2half2_rn(vim[0]-vre[0], vim[1]-vre[1]);
    __half2 c1 = __floats2half2_rn(vim[2]-vre[2], vim[3]-vre[3]);

    __half* RH = RHp;
    *(__half2*)&RH[base + (size_t)tig0 * 8]                   = a0;
    *(__half2*)&RH[base + (size_t)(tig0 + 1) * 8]             = a1;
    *(__half2*)&RH[base + HBSTR + (size_t)tig0 * 8]           = b0;
    *(__half2*)&RH[base + HBSTR + (size_t)(tig0 + 1) * 8]     = b1;
    *(__half2*)&RH[base + 2 * HBSTR + (size_t)tig0 * 8]       = c0;
    *(__half2*)&RH[base + 2 * HBSTR + (size_t)(tig0 + 1) * 8] = c1;
}

__global__ void ew_out(const float* __restrict__ XH, const float* __restrict__ R,
                       const float* __restrict__ h, const float* __restrict__ rb,
                       const float* __restrict__ ib, const float* __restrict__ Z,
                       float* __restrict__ out)
{
    const int i = blockIdx.x * blockDim.x + threadIdx.x;
    const int m = i >> 9;
    const int jj = (i & 511) << 2;

    const size_t HX = (size_t)1024 * 2048, RX = (size_t)1024 * 2048;
    const float* X1 = XH + (size_t)m * 2048;
    const float* R1 = R + (size_t)m * 2048;

    float4 p1 = *(const float4*)&X1[jj],      p2 = *(const float4*)&X1[HX + jj],
           p3 = *(const float4*)&X1[2*HX + jj];
    float4 r1a = *(const float4*)&R1[jj],        r1b = *(const float4*)&R1[3*RX + jj];
    float4 r2a = *(const float4*)&R1[RX + jj],   r2b = *(const float4*)&R1[4*RX + jj];
    float4 r3a = *(const float4*)&R1[2*RX + jj], r3b = *(const float4*)&R1[5*RX + jj];

    float4 hre = *(const float4*)&h[(size_t)m * 4096 + jj];
    float4 him = *(const float4*)&h[(size_t)m * 4096 + 2048 + jj];
    float4 zre = *(const float4*)&Z[(size_t)m * 4096 + jj];
    float4 zim = *(const float4*)&Z[(size_t)m * 4096 + 2048 + jj];
    float4 bhr = *(const float4*)&rb[4096 + jj], bhi = *(const float4*)&ib[4096 + jj];

    float ore[4], oim[4];
#pragma unroll
    for (int c = 0; c < 4; c++) {
        float A1 = (&p1.x)[c], A2 = (&p2.x)[c], A3 = (&p3.x)[c];
        float B1 = (&r1a.x)[c] + (&r1b.x)[c];
        float B2 = (&r2a.x)[c] + (&r2b.x)[c];
        float B3 = (&r3a.x)[c] + (&r3b.x)[c];
        float xre = A1 + A2 + (&bhr.x)[c] + B1 + B2;
        float xim = A3 + A1 - A2 + (&bhi.x)[c] + B3 + B1 - B2;
        float tre = tanhf(xre), tim = tanhf(xim);
        float Zr = (&zre.x)[c], Zi = (&zim.x)[c];
        ore[c] = Zr * (&hre.x)[c] + (1.0f - Zr) * tre;
        oim[c] = Zi * (&him.x)[c] + (1.0f - Zi) * tim;
    }
    *(float4*)&out[(size_t)m * 4096 + jj]        = make_float4(ore[0], ore[1], ore[2], ore[3]);
    *(float4*)&out[(size_t)m * 4096 + 2048 + jj] = make_float4(oim[0], oim[1], oim[2], oim[3]);
}

// --------------------------------------------------------------------- launch
extern "C" void kernel_launch(void* const* d_in, const int* in_sizes, int n_in,
                              void* d_out, int out_size)
{
    const float* inputs = (const float*)d_in[0];
    const float* h_tm1  = (const float*)d_in[1];
    const float* rk     = (const float*)d_in[2];
    const float* ik     = (const float*)d_in[3];
    const float* rrk    = (const float*)d_in[4];
    const float* irk    = (const float*)d_in[5];
    const float* rb     = (const float*)d_in[6];
    const float* ib     = (const float*)d_in[7];
    float* out = (float*)d_out;

    uint4 *pRHF, *pWRH;
    float *pZR, *pXH, *pR, *pZ;
    cudaGetSymbolAddress((void**)&pRHF, g_RHF);
    cudaGetSymbolAddress((void**)&pWRH, g_WRH);
    cudaGetSymbolAddress((void**)&pZR,  g_ZR);
    cudaGetSymbolAddress((void**)&pXH,  g_XH);
    cudaGetSymbolAddress((void**)&pR,   g_R);
    cudaGetSymbolAddress((void**)&pZ,   g_Z);

    cudaFuncSetAttribute(gemm_big,  cudaFuncAttributeMaxDynamicSharedMemorySize, GSMEM2);
    cudaFuncSetAttribute(gemm_frag, cudaFuncAttributeMaxDynamicSharedMemorySize, GSMEM);

    cudaStream_t s1;
    cudaStreamCreateWithFlags(&s1, cudaStreamNonBlocking);
    cudaEvent_t eF, eA, eWRH;
    cudaEventCreateWithFlags(&eF,   cudaEventDisableTiming);
    cudaEventCreateWithFlags(&eA,   cudaEventDisableTiming);
    cudaEventCreateWithFlags(&eWRH, cudaEventDisableTiming);

    // fork
    cudaEventRecord(eF, 0);
    cudaStreamWaitEvent(s1, eF, 0);

    // s1: operand prep, then WRH prep (both memory-bound; overlap s0's prep)
    prep_a<<<1024, 256, 0, s1>>>(inputs, h_tm1);
    cudaEventRecord(eA, s1);
    prep_w_sub<<<1024, 256, 0, s1>>>(rk, ik, rrk, irk, 1);   // WRH
    cudaEventRecord(eWRH, s1);

    // s0: WZR + WH prep, then the big GEMM (zr long CTAs first, XH last)
    prep_w_sub<<<5120, 256>>>(rk, ik, rrk, irk, 0);
    cudaStreamWaitEvent(0, eA, 0);
    gemm_big<<<dim3(3, 8, 24), 256, GSMEM2>>>();
    ew_zr<<<2048, 256>>>(pZR, h_tm1, rb, ib, pZ, (__half*)pRHF);

    cudaStreamWaitEvent(0, eWRH, 0);
    gemm_frag<<<dim3(16, 8, 6), 128, GSMEM>>>(pRHF, pWRH, pR, 2048, 32);
    ew_out<<<2048, 256>>>(pXH, pR, h_tm1, rb, ib, pZ, out);
}

// round 15
// speedup vs baseline: 1.1805x; 1.1805x over previous
#include <cuda_runtime.h>
#include <cuda_fp16.h>
#include <cstdint>
#include <cmath>

// ============================================================================
// CGRU cell, B=1024, UNITS=2048 — Gauss 3-mult complex GEMM, FP16 mma.sync.
// v10 = round-13 kernels (128-thread GEMM, 2 CTA/SM) + split post-GEMM
// pipeline: two half-batch chains (ew_zr -> gemm_frag -> ew_out) on two
// streams, overlapping elementwise with GEMM.
// ============================================================================

#define TU4 512                          // uint4 per 128x32 fp16 tile
#define ASTRIDE ((size_t)128 * TU4)      // u4 per (unit,batch): 128 kb slots
#define HSTRIDE ((size_t)64 * TU4)       // u4 per (unit,batch): 64 kb slots
#define BSTR HSTRIDE

// ------------------------------ scratch (device globals, allocation-free) --
__device__ uint4 g_AH [(size_t)8  * 3 * ASTRIDE];  // [A|H] fragments  (25MB)
__device__ uint4 g_WZR[(size_t)32 * 3 * ASTRIDE];  // [[Kzr],[Rzr]]    (100MB)
__device__ uint4 g_WH [(size_t)16 * 3 * HSTRIDE];  // Kh               (25MB)
__device__ uint4 g_WRH[(size_t)16 * 3 * HSTRIDE];  // Rh               (25MB)
__device__ uint4 g_RHF[(size_t)8  * 3 * HSTRIDE];  // (r*h) fragments  (12.6MB)
__device__ float g_ZR [(size_t)3 * 1024 * 4096];   // zr GEMM out (50MB)
__device__ float g_XH [(size_t)3 * 1024 * 2048];   // x_h GEMM out (25MB)
__device__ float g_R  [(size_t)6 * 1024 * 2048];   // HH GEMM out (split-K x2)
__device__ float g_Z  [(size_t)1024 * 4096];

// ----------------------------------------------------------------- helpers --
__device__ __forceinline__ void cp16s(uint32_t d, const void* s) {
    asm volatile("cp.async.cg.shared.global [%0], [%1], 16;" :: "r"(d), "l"(s));
}
__device__ __forceinline__ uint32_t smem_u32(const void* p) {
    uint32_t a;
    asm("{ .reg .u64 t; cvta.to.shared.u64 t, %1; cvt.u32.u64 %0, t; }" : "=r"(a) : "l"(p));
    return a;
}
__device__ __forceinline__ void mma_f16(float* c, const uint32_t* a, uint32_t b0, uint32_t b1) {
    asm volatile(
        "mma.sync.aligned.m16n8k16.row.col.f32.f16.f16.f32 "
        "{%0,%1,%2,%3},{%4,%5,%6,%7},{%8,%9},{%0,%1,%2,%3};"
        : "+f"(c[0]), "+f"(c[1]), "+f"(c[2]), "+f"(c[3])
        : "r"(a[0]), "r"(a[1]), "r"(a[2]), "r"(a[3]), "r"(b0), "r"(b1));
}
__device__ __forceinline__ uint32_t packh2(float a, float b) {
    __half2 h = __floats2half2_rn(a, b);
    return *(uint32_t*)&h;
}

// ============================================================================
// prep_w_sub: weight fragments.
//   mode 0 (5120 blocks): b<4096 -> WZR (panels 0-31, both matrices);
//                         b>=4096 -> WH (mat0, panels 32-47)
//   mode 1 (1024 blocks): WRH (mat1, panels 32-47)
// ============================================================================
#define PWS 136

__global__ __launch_bounds__(256) void prep_w_sub(
    const float* __restrict__ rk,  const float* __restrict__ ik,
    const float* __restrict__ rrk, const float* __restrict__ irk,
    int mode)
{
    __shared__ float sr[32 * PWS], si[32 * PWS];
    const int tid = threadIdx.x;
    const int b = blockIdx.x;

    int mat, panel, kb;
    if (mode == 0) {
        if (b < 4096) {
            mat = b >> 11;
            const int rem = b & 2047;
            panel = rem >> 6;
            kb = rem & 63;
        } else {
            mat = 0;
            panel = 32 + ((b - 4096) >> 6);
            kb = b & 63;
        }
    } else {
        mat = 1;
        panel = 32 + (b >> 6);
        kb = b & 63;
    }

    const float* Wr = mat ? rrk : rk;
    const float* Wi = mat ? irk : ik;
    const size_t gbase = (size_t)(kb * 32) * 6144 + panel * 128;

#pragma unroll
    for (int t = 0; t < 4; t++) {
        const int idx = tid + t * 256;
        const int row = idx >> 5, c4 = idx & 31;
        const size_t ga = gbase + (size_t)row * 6144 + c4 * 4;
        *(float4*)&sr[row * PWS + c4 * 4] = *(const float4*)&Wr[ga];
        *(float4*)&si[row * PWS + c4 * 4] = *(const float4*)&Wi[ga];
    }
    __syncthreads();

    uint4* O;
    size_t obase, bstr;
    if (panel < 32) {
        O = g_WZR;
        obase = ((size_t)(panel * 3) * 128 + mat * 64 + kb) * TU4;
        bstr = ASTRIDE;
    } else {
        O = mat ? g_WRH : g_WH;
        obase = ((size_t)((panel - 32) * 3) * 64 + kb) * TU4;
        bstr = HSTRIDE;
    }

#pragma unroll
    for (int t = 0; t < 2; t++) {
        const int x = tid + t * 256;
        const int n16 = x >> 6, k16 = (x >> 5) & 1, lane = x & 31;
        const int grp = lane >> 2, tig = lane & 3;
        const int c = n16 * 16 + grp;
        const int k0 = k16 * 16 + tig * 2;

        float wr[8], wi[8];
#pragma unroll
        for (int hc = 0; hc < 2; hc++) {
            const int cc = c + hc * 8;
            wr[hc*4+0] = sr[k0 * PWS + cc];       wi[hc*4+0] = si[k0 * PWS + cc];
            wr[hc*4+1] = sr[(k0+1) * PWS + cc];   wi[hc*4+1] = si[(k0+1) * PWS + cc];
            wr[hc*4+2] = sr[(k0+8) * PWS + cc];   wi[hc*4+2] = si[(k0+8) * PWS + cc];
            wr[hc*4+3] = sr[(k0+9) * PWS + cc];   wi[hc*4+3] = si[(k0+9) * PWS + cc];
        }
        uint4 v0, v1, v2;
        v0.x = packh2(wr[0], wr[1]); v0.y = packh2(wr[2], wr[3]);
        v0.z = packh2(wr[4], wr[5]); v0.w = packh2(wr[6], wr[7]);
        v1.x = packh2(wi[0], wi[1]); v1.y = packh2(wi[2], wi[3]);
        v1.z = packh2(wi[4], wi[5]); v1.w = packh2(wi[6], wi[7]);
        v2.x = packh2(wr[0]+wi[0], wr[1]+wi[1]); v2.y = packh2(wr[2]+wi[2], wr[3]+wi[3]);
        v2.z = packh2(wr[4]+wi[4], wr[5]+wi[5]); v2.w = packh2(wr[6]+wi[6], wr[7]+wi[7]);

        O[obase + x]            = v0;
        O[obase + bstr + x]     = v1;
        O[obase + 2 * bstr + x] = v2;
    }
}

// ============================================================================
// prep_a: A-fragments into concat layout [mp(8)][batch(3)][kb(128)][512 u4]:
//   src 0 (inputs) -> kb 0-63, src 1 (h) -> kb 64-127.
// ============================================================================
#define PAS 36

__global__ __launch_bounds__(256) void prep_a(
    const float* __restrict__ in0, const float* __restrict__ in1)
{
    __shared__ float s0[128 * PAS], s1[128 * PAS];
    const int tid = threadIdx.x;
    const int b = blockIdx.x;
    const int src = b >> 9;
    const int rem = b & 511;
    const int mp = rem >> 6;
    const int kb = rem & 63;

    const float* A = src ? in1 : in0;

#pragma unroll
    for (int t = 0; t < 8; t++) {
        const int idx = tid + t * 256;
        const int half_ = idx >> 10;
        const int i2 = idx & 1023;
        const int row = i2 >> 3, c4 = i2 & 7;
        const float4 v = *(const float4*)&A[(size_t)(mp * 128 + row) * 4096
                                            + half_ * 2048 + kb * 32 + c4 * 4];
        float* s = half_ ? s1 : s0;
        *(float4*)&s[row * PAS + c4 * 4] = v;
    }
    __syncthreads();

    const size_t obase = ((size_t)(mp * 3) * 128 + src * 64 + kb) * TU4;

#pragma unroll
    for (int t = 0; t < 2; t++) {
        const int x = tid + t * 256;
        const int m16 = x >> 6, k16 = (x >> 5) & 1, lane = x & 31;
        const int grp = lane >> 2, tig = lane & 3;
        const int r = m16 * 16 + grp;
        const int k0 = k16 * 16 + tig * 2;

        float re[8], im[8];
#pragma unroll
        for (int hk = 0; hk < 2; hk++) {
            const int kk = k0 + hk * 8;
            re[hk*4+0] = s0[r * PAS + kk];         im[hk*4+0] = s1[r * PAS + kk];
            re[hk*4+1] = s0[r * PAS + kk + 1];     im[hk*4+1] = s1[r * PAS + kk + 1];
            re[hk*4+2] = s0[(r+8) * PAS + kk];     im[hk*4+2] = s1[(r+8) * PAS + kk];
            re[hk*4+3] = s0[(r+8) * PAS + kk + 1]; im[hk*4+3] = s1[(r+8) * PAS + kk + 1];
        }
        uint4 v0, v1, v2;
        v0.x = packh2(re[0], re[1]); v0.y = packh2(re[2], re[3]);
        v0.z = packh2(re[4], re[5]); v0.w = packh2(re[6], re[7]);
        v1.x = packh2(im[0], im[1]); v1.y = packh2(im[2], im[3]);
        v1.z = packh2(im[4], im[5]); v1.w = packh2(im[6], im[7]);
        v2.x = packh2(im[0]-re[0], im[1]-re[1]); v2.y = packh2(im[2]-re[2], im[3]-re[3]);
        v2.z = packh2(im[4]-re[4], im[5]-re[5]); v2.w = packh2(im[6]-re[6], im[7]-re[7]);

        g_AH[obase + x]               = v0;
        g_AH[obase + ASTRIDE + x]     = v1;
        g_AH[obase + 2 * ASTRIDE + x] = v2;
    }
}

// ============================================================================
// GEMM core body (128-thread, 2 CTA/SM — proven config)
// ============================================================================
#define STAGES 4
#define STG_BYTES 16384
#define GSMEM (STAGES * STG_BYTES)

#define ISSUE(kb) do {                                                         \
    const uint32_t _st = sbase + ((kb) % STAGES) * STG_BYTES;                  \
    const uint4* _sa = At + (size_t)(kb) * TU4;                                \
    const uint4* _sb = Bt + (size_t)(kb) * TU4;                                \
    _Pragma("unroll")                                                          \
    for (int _i = 0; _i < 4; _i++) {                                           \
        const int _o = tid + _i * 128;                                         \
        cp16s(_st + _o * 16, _sa + _o);                                        \
        cp16s(_st + 8192 + _o * 16, _sb + _o);                                 \
    }                                                                          \
} while (0)

#define GEMM_BODY(At, Bt, Cb, Nld, n0, kIters)                                 \
    const int wm4 = (wid & 1) * 4;                                             \
    const int wn4 = (wid >> 1) * 4;                                            \
    float acc[4][8][4];                                                        \
    _Pragma("unroll")                                                          \
    for (int a = 0; a < 4; a++)                                                \
        _Pragma("unroll")                                                      \
        for (int b2 = 0; b2 < 8; b2++)                                         \
            _Pragma("unroll")                                                  \
            for (int c = 0; c < 4; c++) acc[a][b2][c] = 0.0f;                  \
    ISSUE(0);                                                                  \
    asm volatile("cp.async.commit_group;" ::: "memory");                       \
    ISSUE(1);                                                                  \
    asm volatile("cp.async.commit_group;" ::: "memory");                       \
    ISSUE(2);                                                                  \
    asm volatile("cp.async.commit_group;" ::: "memory");                       \
    uint4 af[2][4], bf[2][4];                                                  \
    for (int kb = 0; kb < kIters; ++kb) {                                      \
        asm volatile("cp.async.wait_group 2;" ::: "memory");                   \
        __syncthreads();                                                       \
        const uint4* As = smu + (kb % STAGES) * 1024;                          \
        const uint4* Bs = As + 512;                                            \
        _Pragma("unroll")                                                      \
        for (int t = 0; t < 4; ++t) {                                          \
            af[0][t] = As[((wm4 + t) * 2) * 32 + lane];                        \
            bf[0][t] = Bs[((wn4 + t) * 2) * 32 + lane];                        \
        }                                                                      \
        _Pragma("unroll")                                                      \
        for (int ks = 0; ks < 2; ++ks) {                                       \
            const int cur = ks;                                                \
            if (ks == 0) {                                                     \
                _Pragma("unroll")                                              \
                for (int t = 0; t < 4; ++t) {                                  \
                    af[1][t] = As[((wm4 + t) * 2 + 1) * 32 + lane];            \
                    bf[1][t] = Bs[((wn4 + t) * 2 + 1) * 32 + lane];            \
                }                                                              \
            }                                                                  \
            _Pragma("unroll")                                                  \
            for (int tm = 0; tm < 4; ++tm) {                                   \
                const uint32_t* a = (const uint32_t*)&af[cur][tm];             \
                _Pragma("unroll")                                              \
                for (int p = 0; p < 4; ++p) {                                  \
                    const uint32_t* bu = (const uint32_t*)&bf[cur][p];         \
                    mma_f16(acc[tm][p * 2],     a, bu[0], bu[1]);              \
                    mma_f16(acc[tm][p * 2 + 1], a, bu[2], bu[3]);              \
                }                                                              \
            }                                                                  \
        }                                                                      \
        if (kb + 3 < kIters) ISSUE(kb + 3);                                    \
        asm volatile("cp.async.commit_group;" ::: "memory");                   \
    }                                                                          \
    _Pragma("unroll")                                                          \
    for (int tm = 0; tm < 4; ++tm) {                                           \
        _Pragma("unroll")                                                      \
        for (int tn = 0; tn < 8; ++tn) {                                       \
            const int m0 = mp * 128 + (wid & 1) * 64 + tm * 16 + grp;          \
            const int nn = n0 + (wid >> 1) * 64 + tn * 8 + tig * 2;            \
            *(float2*)&Cb[(size_t)m0 * Nld + nn]       = make_float2(acc[tm][tn][0], acc[tm][tn][1]); \
            *(float2*)&Cb[(size_t)(m0 + 8) * Nld + nn] = make_float2(acc[tm][tn][2], acc[tm][tn][3]); \
        }                                                                      \
    }

// gemm_big: grid (3, 8, 48) — x=batch, y=mp, z=panel selector.
// z<32 -> zr panel (K=128 iters); z>=32 -> XH panel (K=64 iters, last).
__global__ __launch_bounds__(128, 2) void gemm_big()
{
    extern __shared__ uint4 smu[];
    const uint32_t sbase = smem_u32(smu);
    const int tid = threadIdx.x, wid = tid >> 5, lane = tid & 31;
    const int grp = lane >> 2, tig = lane & 3;
    const int batch = blockIdx.x;
    const int mp = blockIdx.y;
    const int pz = blockIdx.z;

    const uint4* At = g_AH + (size_t)(mp * 3 + batch) * ASTRIDE;
    if (pz < 32) {
        const uint4* Bt = g_WZR + (size_t)(pz * 3 + batch) * ASTRIDE;
        float* Cb = g_ZR + (size_t)batch * 1024 * 4096;
        const int n0 = pz * 128;
        GEMM_BODY(At, Bt, Cb, 4096, n0, 128)
    } else {
        const int px = pz - 32;
        const uint4* Bt = g_WH + (size_t)(px * 3 + batch) * HSTRIDE;
        float* Cb = g_XH + (size_t)batch * 1024 * 2048;
        const int n0 = px * 128;
        GEMM_BODY(At, Bt, Cb, 2048, n0, 64)
    }
}

// gemm_frag: HH GEMM (A=RHF, B=WRH), split-K x2, half-batch via mpOff.
// grid (16, 4, 6)
__global__ __launch_bounds__(128, 2) void gemm_frag(
    const uint4* __restrict__ Ap, const uint4* __restrict__ Bp,
    float* __restrict__ C, int Nld, int kIters, int mpOff)
{
    extern __shared__ uint4 smu[];
    const uint32_t sbase = smem_u32(smu);
    const int tid = threadIdx.x, wid = tid >> 5, lane = tid & 31;
    const int grp = lane >> 2, tig = lane & 3;
    const int mp = blockIdx.y + mpOff;
    const int z = blockIdx.z;
    const int batch = z % 3, half_ = z / 3;
    const int panel = blockIdx.x;
    const int kO = half_ * kIters;

    const uint4* At = Ap + (size_t)(mp * 3 + batch) * BSTR + (size_t)kO * TU4;
    const uint4* Bt = Bp + (size_t)(panel * 3 + batch) * BSTR + (size_t)kO * TU4;
    float* Cb = C + (size_t)z * 1024 * Nld;
    const int n0 = panel * 128;
    GEMM_BODY(At, Bt, Cb, Nld, n0, kIters)
}

// ---------------------------------------------------------------- elementwise
__device__ __forceinline__ float hsig(float x) {
    return fminf(fmaxf(0.2f * x + 0.5f, 0.0f), 1.0f);
}

// half-batch: 1024 blocks, rows [m_base, m_base+512)
__global__ void ew_zr(const float* __restrict__ ZR, const float* __restrict__ h,
                      const float* __restrict__ rb, const float* __restrict__ ib,
                      float* __restrict__ Z, __half* __restrict__ RHp, int m_base)
{
    const int i = blockIdx.x * blockDim.x + threadIdx.x;
    const int m = m_base + (i >> 9);
    const int jj = (i & 511) << 2;

    const size_t PX = (size_t)1024 * 4096;
    const float* Z1 = ZR + (size_t)m * 4096;

    float4 p1z = *(const float4*)&Z1[jj],        p2z = *(const float4*)&Z1[PX + jj],
           p3z = *(const float4*)&Z1[2*PX + jj];
    float4 p1r = *(const float4*)&Z1[2048 + jj], p2r = *(const float4*)&Z1[PX + 2048 + jj],
           p3r = *(const float4*)&Z1[2*PX + 2048 + jj];

    float4 hre = *(const float4*)&h[(size_t)m * 4096 + jj];
    float4 him = *(const float4*)&h[(size_t)m * 4096 + 2048 + jj];
    float4 bzr = *(const float4*)&rb[jj],        bzi = *(const float4*)&ib[jj];
    float4 brr = *(const float4*)&rb[2048 + jj], bri = *(const float4*)&ib[2048 + jj];

    float zre[4], zim[4], vre[4], vim[4];
#pragma unroll
    for (int c = 0; c < 4; c++) {
        float P1z = (&p1z.x)[c], P2z = (&p2z.x)[c], P3z = (&p3z.x)[c];
        float P1r = (&p1r.x)[c], P2r = (&p2r.x)[c], P3r = (&p3r.x)[c];
        zre[c] = hsig(P1z + P2z + (&bzr.x)[c]);
        zim[c] = hsig(P3z + P1z - P2z + (&bzi.x)[c]);
        float rre = hsig(P1r + P2r + (&brr.x)[c]);
        float rim = hsig(P3r + P1r - P2r + (&bri.x)[c]);
        vre[c] = rre * (&hre.x)[c];
        vim[c] = rim * (&him.x)[c];
    }

    *(float4*)&Z[(size_t)m * 4096 + jj]        = make_float4(zre[0], zre[1], zre[2], zre[3]);
    *(float4*)&Z[(size_t)m * 4096 + 2048 + jj] = make_float4(zim[0], zim[1], zim[2], zim[3]);

    const int mp = m >> 7, m16 = (m >> 4) & 7;
    const int rr = m & 15, grpm = rr & 7, hi = rr >> 3;
    const int kb = jj >> 5, k16 = (jj >> 4) & 1;
    const int jmk = jj & 15, tig0 = (jmk & 7) >> 1, hiK = jmk >> 3;
    const int pos = hiK * 4 + hi * 2;
    const size_t HBSTR = (size_t)64 * 4096;
    size_t base = ((size_t)(mp * 3) * 64 + kb) * 4096
                + ((size_t)((m16 * 2 + k16) * 32 + grpm * 4) * 8) + pos;

    __half2 a0 = __floats2half2_rn(vre[0], vre[1]);
    __half2 a1 = __floats2half2_rn(vre[2], vre[3]);
    __half2 b0 = __floats2half2_rn(vim[0], vim[1]);
    __half2 b1 = __floats2half2_rn(vim[2], vim[3]);
    __half2 c0 = __floats2half2_rn(vim[0]-vre[0], vim[1]-vre[1]);
    __half2 c1 = __floats2half2_rn(vim[2]-vre[2], vim[3]-vre[3]);

    __half* RH = RHp;
    *(__half2*)&RH[base + (size_t)tig0 * 8]                   = a0;
    *(__half2*)&RH[base + (size_t)(tig0 + 1) * 8]             = a1;
    *(__half2*)&RH[base + HBSTR + (size_t)tig0 * 8]           = b0;
    *(__half2*)&RH[base + HBSTR + (size_t)(tig0 + 1) * 8]     = b1;
    *(__half2*)&RH[base + 2 * HBSTR + (size_t)tig0 * 8]       = c0;
    *(__half2*)&RH[base + 2 * HBSTR + (size_t)(tig0 + 1) * 8] = c1;
}

// half-batch: 1024 blocks, rows [m_base, m_base+512)
__global__ void ew_out(const float* __restrict__ XH, const float* __restrict__ R,
                       const float* __restrict__ h, const float* __restrict__ rb,
                       const float* __restrict__ ib, const float* __restrict__ Z,
                       float* __restrict__ out, int m_base)
{
    const int i = blockIdx.x * blockDim.x + threadIdx.x;
    const int m = m_base + (i >> 9);
    const int jj = (i & 511) << 2;

    const size_t HX = (size_t)1024 * 2048, RX = (size_t)1024 * 2048;
    const float* X1 = XH + (size_t)m * 2048;
    const float* R1 = R + (size_t)m * 2048;

    float4 p1 = *(const float4*)&X1[jj],      p2 = *(const float4*)&X1[HX + jj],
           p3 = *(const float4*)&X1[2*HX + jj];
    float4 r1a = *(const float4*)&R1[jj],        r1b = *(const float4*)&R1[3*RX + jj];
    float4 r2a = *(const float4*)&R1[RX + jj],   r2b = *(const float4*)&R1[4*RX + jj];
    float4 r3a = *(const float4*)&R1[2*RX + jj], r3b = *(const float4*)&R1[5*RX + jj];

    float4 hre = *(const float4*)&h[(size_t)m * 4096 + jj];
    float4 him = *(const float4*)&h[(size_t)m * 4096 + 2048 + jj];
    float4 zre = *(const float4*)&Z[(size_t)m * 4096 + jj];
    float4 zim = *(const float4*)&Z[(size_t)m * 4096 + 2048 + jj];
    float4 bhr = *(const float4*)&rb[4096 + jj], bhi = *(const float4*)&ib[4096 + jj];

    float ore[4], oim[4];
#pragma unroll
    for (int c = 0; c < 4; c++) {
        float A1 = (&p1.x)[c], A2 = (&p2.x)[c], A3 = (&p3.x)[c];
        float B1 = (&r1a.x)[c] + (&r1b.x)[c];
        float B2 = (&r2a.x)[c] + (&r2b.x)[c];
        float B3 = (&r3a.x)[c] + (&r3b.x)[c];
        float xre = A1 + A2 + (&bhr.x)[c] + B1 + B2;
        float xim = A3 + A1 - A2 + (&bhi.x)[c] + B3 + B1 - B2;
        float tre = tanhf(xre), tim = tanhf(xim);
        float Zr = (&zre.x)[c], Zi = (&zim.x)[c];
        ore[c] = Zr * (&hre.x)[c] + (1.0f - Zr) * tre;
        oim[c] = Zi * (&him.x)[c] + (1.0f - Zi) * tim;
    }
    *(float4*)&out[(size_t)m * 4096 + jj]        = make_float4(ore[0], ore[1], ore[2], ore[3]);
    *(float4*)&out[(size_t)m * 4096 + 2048 + jj] = make_float4(oim[0], oim[1], oim[2], oim[3]);
}

// --------------------------------------------------------------------- launch
extern "C" void kernel_launch(void* const* d_in, const int* in_sizes, int n_in,
                              void* d_out, int out_size)
{
    const float* inputs = (const float*)d_in[0];
    const float* h_tm1  = (const float*)d_in[1];
    const float* rk     = (const float*)d_in[2];
    const float* ik     = (const float*)d_in[3];
    const float* rrk    = (const float*)d_in[4];
    const float* irk    = (const float*)d_in[5];
    const float* rb     = (const float*)d_in[6];
    const float* ib     = (const float*)d_in[7];
    float* out = (float*)d_out;

    uint4 *pRHF, *pWRH;
    float *pZR, *pXH, *pR, *pZ;
    cudaGetSymbolAddress((void**)&pRHF, g_RHF);
    cudaGetSymbolAddress((void**)&pWRH, g_WRH);
    cudaGetSymbolAddress((void**)&pZR,  g_ZR);
    cudaGetSymbolAddress((void**)&pXH,  g_XH);
    cudaGetSymbolAddress((void**)&pR,   g_R);
    cudaGetSymbolAddress((void**)&pZ,   g_Z);

    cudaFuncSetAttribute(gemm_big,  cudaFuncAttributeMaxDynamicSharedMemorySize, GSMEM);
    cudaFuncSetAttribute(gemm_frag, cudaFuncAttributeMaxDynamicSharedMemorySize, GSMEM);

    cudaStream_t s1;
    cudaStreamCreateWithFlags(&s1, cudaStreamNonBlocking);
    cudaEvent_t eF, eA, eWRH, eBig, eEnd;
    cudaEventCreateWithFlags(&eF,   cudaEventDisableTiming);
    cudaEventCreateWithFlags(&eA,   cudaEventDisableTiming);
    cudaEventCreateWithFlags(&eWRH, cudaEventDisableTiming);
    cudaEventCreateWithFlags(&eBig, cudaEventDisableTiming);
    cudaEventCreateWithFlags(&eEnd, cudaEventDisableTiming);

    // fork
    cudaEventRecord(eF, 0);
    cudaStreamWaitEvent(s1, eF, 0);

    // s1: operand prep + WRH prep (memory-bound; overlaps s0's prep)
    prep_a<<<1024, 256, 0, s1>>>(inputs, h_tm1);
    cudaEventRecord(eA, s1);
    prep_w_sub<<<1024, 256, 0, s1>>>(rk, ik, rrk, irk, 1);   // WRH
    cudaEventRecord(eWRH, s1);

    // s0: WZR + WH prep, then the big GEMM (zr first, XH last)
    prep_w_sub<<<5120, 256>>>(rk, ik, rrk, irk, 0);
    cudaStreamWaitEvent(0, eA, 0);
    gemm_big<<<dim3(3, 8, 48), 128, GSMEM>>>();
    cudaEventRecord(eBig, 0);

    // chain 0 on s0: rows 0-511 (needs WRH for gemm_frag)
    cudaStreamWaitEvent(0, eWRH, 0);
    ew_zr<<<1024, 256>>>(pZR, h_tm1, rb, ib, pZ, (__half*)pRHF, 0);
    gemm_frag<<<dim3(16, 4, 6), 128, GSMEM>>>(pRHF, pWRH, pR, 2048, 32, 0);
    ew_out<<<1024, 256>>>(pXH, pR, h_tm1, rb, ib, pZ, out, 0);

    // chain 1 on s1: rows 512-1023 (WRH already on s1; wait for gemm_big)
    cudaStreamWaitEvent(s1, eBig, 0);
    ew_zr<<<1024, 256, 0, s1>>>(pZR, h_tm1, rb, ib, pZ, (__half*)pRHF, 512);
    gemm_frag<<<dim3(16, 4, 6), 128, GSMEM, s1>>>(pRHF, pWRH, pR, 2048, 32, 4);
    ew_out<<<1024, 256, 0, s1>>>(pXH, pR, h_tm1, rb, ib, pZ, out, 512);
    cudaEventRecord(eEnd, s1);

    // join
    cudaStreamWaitEvent(0, eEnd, 0);
}